// round 6
// baseline (speedup 1.0000x reference)
#include <cuda_runtime.h>

#define NN 50000
#define EE 800000
#define IN1 128
#define HC1 256   // H1 * CC
#define H1 4
#define CC 64
#define NEG 0.2f
#define NB_SCAN 196   // ceil(50000/256)

// ---------------- scratch (device globals; allocation-free) ----------------
__device__ float g_h1[NN * HC1];     // layer1 features h = x@W1
__device__ float g_agg1[NN * HC1];   // relu(layer1 out) = layer2 input
__device__ float g_h2[NN * CC];      // layer2 features
__device__ float g_as1[NN * H1];
__device__ float g_ad1[NN * H1];
__device__ float g_as2[NN];
__device__ float g_ad2[NN];
__device__ float g_wex1[EE * H1];
__device__ float g_wex2[EE];
__device__ int   g_deg[NN];
__device__ int   g_off[NN + 1];
__device__ int   g_cur[NN];
__device__ int   g_csr_src[EE];
__device__ int   g_csr_dst[EE];
__device__ int   g_part[NB_SCAN];
__device__ int   g_pofs[NB_SCAN];
__device__ int   g_is64;

__device__ __forceinline__ float leaky(float v) {
    return v > 0.f ? v : NEG * v;
}

// ---- packed f32x2 helpers (sm_100+) ----
__device__ __forceinline__ unsigned long long pk2(float lo, float hi) {
    unsigned long long r;
    asm("mov.b64 %0, {%1, %2};" : "=l"(r) : "f"(lo), "f"(hi));
    return r;
}
__device__ __forceinline__ void fma2(unsigned long long& d,
                                     unsigned long long a, unsigned long long b) {
    asm("fma.rn.f32x2 %0, %1, %2, %0;" : "+l"(d) : "l"(a), "l"(b));
}
__device__ __forceinline__ void upk2(unsigned long long v, float& lo, float& hi) {
    asm("mov.b64 {%0, %1}, %2;" : "=f"(lo), "=f"(hi) : "l"(v));
}

// edge_index may be int32 (JAX x64 disabled) or int64. Detect at runtime.
__global__ void detect_kernel(const void* __restrict__ ei) {
    const unsigned long long* p = (const unsigned long long*)ei;
    int is64 = 1;
    for (int i = 0; i < 64; i++) {
        if ((p[i] >> 32) != 0ull) { is64 = 0; break; }
    }
    g_is64 = is64;
}

__device__ __forceinline__ int edge_at(const void* __restrict__ ei, int idx) {
    if (g_is64) return (int)((const long long*)ei)[idx];
    return ((const int*)ei)[idx];
}

// ---------------- CSR build ----------------
__global__ void zero_deg_kernel() {
    int i = blockIdx.x * blockDim.x + threadIdx.x;
    if (i < NN) g_deg[i] = 0;
}

__global__ void count_kernel(const void* __restrict__ ei) {
    int e = blockIdx.x * blockDim.x + threadIdx.x;
    if (e < EE) {
        int dst = edge_at(ei, EE + e);
        atomicAdd(&g_deg[dst], 1);
    }
}

__global__ __launch_bounds__(256) void scan_partial_kernel() {
    int b = blockIdx.x;
    int tid = threadIdx.x;
    int idx = b * 256 + tid;
    int v = (idx < NN) ? g_deg[idx] : 0;
    #pragma unroll
    for (int o = 16; o > 0; o >>= 1) v += __shfl_xor_sync(0xFFFFFFFF, v, o);
    __shared__ int wsum[8];
    if ((tid & 31) == 0) wsum[tid >> 5] = v;
    __syncthreads();
    if (tid == 0) {
        int s = 0;
        #pragma unroll
        for (int i = 0; i < 8; i++) s += wsum[i];
        g_part[b] = s;
    }
}

__global__ __launch_bounds__(256) void scan_tops_kernel() {
    int tid = threadIdx.x;
    int v = (tid < NB_SCAN) ? g_part[tid] : 0;
    int lane = tid & 31, w = tid >> 5;
    int x = v;
    #pragma unroll
    for (int o = 1; o < 32; o <<= 1) {
        int t = __shfl_up_sync(0xFFFFFFFF, x, o);
        if (lane >= o) x += t;
    }
    __shared__ int wsum[8];
    if (lane == 31) wsum[w] = x;
    __syncthreads();
    if (tid == 0) {
        int run = 0;
        #pragma unroll
        for (int i = 0; i < 8; i++) { int t = wsum[i]; wsum[i] = run; run += t; }
        g_off[NN] = run;
    }
    __syncthreads();
    if (tid < NB_SCAN) g_pofs[tid] = x - v + wsum[w];
}

__global__ __launch_bounds__(256) void scan_apply_kernel() {
    int b = blockIdx.x;
    int tid = threadIdx.x;
    int idx = b * 256 + tid;
    int v = (idx < NN) ? g_deg[idx] : 0;
    int lane = tid & 31, w = tid >> 5;
    int x = v;
    #pragma unroll
    for (int o = 1; o < 32; o <<= 1) {
        int t = __shfl_up_sync(0xFFFFFFFF, x, o);
        if (lane >= o) x += t;
    }
    __shared__ int wsum[8];
    if (lane == 31) wsum[w] = x;
    __syncthreads();
    if (tid == 0) {
        int run = 0;
        #pragma unroll
        for (int i = 0; i < 8; i++) { int t = wsum[i]; wsum[i] = run; run += t; }
    }
    __syncthreads();
    if (idx < NN) {
        int exc = x - v + wsum[w] + g_pofs[b];
        g_off[idx] = exc;
        g_cur[idx] = exc;
    }
}

// scatter + layer1 edge weights fused (requires as1/ad1 -> runs after gemm1)
__global__ void scatter_kernel(const void* __restrict__ ei) {
    int e = blockIdx.x * blockDim.x + threadIdx.x;
    if (e < EE) {
        int src = edge_at(ei, e);
        int dst = edge_at(ei, EE + e);
        int pos = atomicAdd(&g_cur[dst], 1);
        g_csr_src[pos] = src;
        g_csr_dst[pos] = dst;
        float4 a = *(const float4*)(g_as1 + src * 4);
        float4 d = *(const float4*)(g_ad1 + dst * 4);
        float4 w;
        w.x = expf(leaky(a.x + d.x));
        w.y = expf(leaky(a.y + d.y));
        w.z = expf(leaky(a.z + d.z));
        w.w = expf(leaky(a.w + d.w));
        *(float4*)(g_wex1 + (size_t)pos * 4) = w;
    }
}

// ------- GEMM (f32x2 packed) + fused alpha epilogue -------
// Tile: 128 rows x 64 cols, 128 threads, microtile 8x8.
// One block covers a full head slice -> alpha reduction in epilogue.
template <int K, int NC, int H>
__device__ __forceinline__ void gemm_alpha_body(
    const float* __restrict__ A, const float* __restrict__ B,
    float* __restrict__ C,
    const float* __restrict__ attS, const float* __restrict__ attD,
    float* __restrict__ as_, float* __restrict__ ad_)
{
    __shared__ float As[16][128];
    __shared__ float Bs[16][64];
    int tid = threadIdx.x;         // 0..127
    int ty = tid >> 3;             // 0..15 (8 rows each)
    int tx = tid & 7;              // 0..7  (8 cols each)
    int m0 = blockIdx.x * 128;
    int hh = blockIdx.y;           // head (64 cols per block)
    int n0 = hh * 64;

    unsigned long long acc2[4][8];
    #pragma unroll
    for (int p = 0; p < 4; p++)
        #pragma unroll
        for (int j = 0; j < 8; j++) acc2[p][j] = 0ull;

    for (int k0 = 0; k0 < K; k0 += 16) {
        // A tile: thread tid loads row m0+tid, 16 floats
        {
            int gr = m0 + tid;
            float4 v[4];
            if (gr < NN) {
                const float4* ap = (const float4*)(A + (size_t)gr * K + k0);
                #pragma unroll
                for (int f = 0; f < 4; f++) v[f] = ap[f];
            } else {
                #pragma unroll
                for (int f = 0; f < 4; f++) v[f] = make_float4(0.f, 0.f, 0.f, 0.f);
            }
            #pragma unroll
            for (int f = 0; f < 4; f++) {
                As[f * 4 + 0][tid] = v[f].x;
                As[f * 4 + 1][tid] = v[f].y;
                As[f * 4 + 2][tid] = v[f].z;
                As[f * 4 + 3][tid] = v[f].w;
            }
        }
        // B tile: 16x64 floats = 256 float4, 2 per thread (cols n0..n0+63)
        {
            #pragma unroll
            for (int q = 0; q < 2; q++) {
                int f = tid + q * 128;
                int kr = f >> 4;
                int c4 = f & 15;
                const float4* bp = (const float4*)(B + (size_t)(k0 + kr) * NC + n0 + c4 * 4);
                *(float4*)&Bs[kr][c4 * 4] = *bp;
            }
        }
        __syncthreads();
        #pragma unroll
        for (int kk = 0; kk < 16; kk++) {
            unsigned long long ap[4];
            #pragma unroll
            for (int p = 0; p < 4; p++)
                ap[p] = *(const unsigned long long*)&As[kk][ty * 8 + 2 * p];
            float4 b0 = *(const float4*)&Bs[kk][tx * 8];
            float4 b1 = *(const float4*)&Bs[kk][tx * 8 + 4];
            unsigned long long bb[8];
            bb[0] = pk2(b0.x, b0.x); bb[1] = pk2(b0.y, b0.y);
            bb[2] = pk2(b0.z, b0.z); bb[3] = pk2(b0.w, b0.w);
            bb[4] = pk2(b1.x, b1.x); bb[5] = pk2(b1.y, b1.y);
            bb[6] = pk2(b1.z, b1.z); bb[7] = pk2(b1.w, b1.w);
            #pragma unroll
            for (int p = 0; p < 4; p++)
                #pragma unroll
                for (int j = 0; j < 8; j++)
                    fma2(acc2[p][j], ap[p], bb[j]);
        }
        __syncthreads();
    }

    // attention vectors for this thread's 8 columns
    float aS[8], aD[8];
    #pragma unroll
    for (int j = 0; j < 8; j++) {
        aS[j] = attS[hh * 64 + tx * 8 + j];
        aD[j] = attD[hh * 64 + tx * 8 + j];
    }

    float ds[8], dd[8];
    #pragma unroll
    for (int i = 0; i < 8; i++) { ds[i] = 0.f; dd[i] = 0.f; }

    // unpack, store C, accumulate alpha partials
    #pragma unroll
    for (int p = 0; p < 4; p++) {
        float lo[8], hi[8];
        #pragma unroll
        for (int j = 0; j < 8; j++) upk2(acc2[p][j], lo[j], hi[j]);
        int r0 = m0 + ty * 8 + 2 * p;
        if (r0 < NN) {
            float4 u = make_float4(lo[0], lo[1], lo[2], lo[3]);
            float4 v = make_float4(lo[4], lo[5], lo[6], lo[7]);
            *(float4*)(C + (size_t)r0 * (64 * H) + n0 + tx * 8) = u;
            *(float4*)(C + (size_t)r0 * (64 * H) + n0 + tx * 8 + 4) = v;
        }
        if (r0 + 1 < NN) {
            float4 u = make_float4(hi[0], hi[1], hi[2], hi[3]);
            float4 v = make_float4(hi[4], hi[5], hi[6], hi[7]);
            *(float4*)(C + (size_t)(r0 + 1) * (64 * H) + n0 + tx * 8) = u;
            *(float4*)(C + (size_t)(r0 + 1) * (64 * H) + n0 + tx * 8 + 4) = v;
        }
        #pragma unroll
        for (int j = 0; j < 8; j++) {
            ds[2 * p]     += lo[j] * aS[j];
            dd[2 * p]     += lo[j] * aD[j];
            ds[2 * p + 1] += hi[j] * aS[j];
            dd[2 * p + 1] += hi[j] * aD[j];
        }
    }

    // reduce over the 8 tx lanes (consecutive lanes, xor 1,2,4)
    #pragma unroll
    for (int o = 1; o < 8; o <<= 1) {
        #pragma unroll
        for (int i = 0; i < 8; i++) {
            ds[i] += __shfl_xor_sync(0xFFFFFFFF, ds[i], o);
            dd[i] += __shfl_xor_sync(0xFFFFFFFF, dd[i], o);
        }
    }
    if (tx == 0) {
        #pragma unroll
        for (int i = 0; i < 8; i++) {
            int r = m0 + ty * 8 + i;
            if (r < NN) {
                as_[r * H + hh] = ds[i];
                ad_[r * H + hh] = dd[i];
            }
        }
    }
}

__global__ __launch_bounds__(128) void gemm1_kernel(
    const float* __restrict__ A, const float* __restrict__ B,
    const float* __restrict__ attS, const float* __restrict__ attD) {
    gemm_alpha_body<IN1, HC1, H1>(A, B, g_h1, attS, attD, g_as1, g_ad1);
}
__global__ __launch_bounds__(128) void gemm2_kernel(
    const float* __restrict__ B,
    const float* __restrict__ attS, const float* __restrict__ attD) {
    gemm_alpha_body<HC1, CC, 1>(g_agg1, B, g_h2, attS, attD, g_as2, g_ad2);
}

// ---------------- layer2 edge weights ----------------
__global__ void edge_kernel_l2() {
    int e = blockIdx.x * blockDim.x + threadIdx.x;
    if (e >= EE) return;
    int src = g_csr_src[e];
    int dst = g_csr_dst[e];
    g_wex2[e] = expf(leaky(g_as2[src] + g_ad2[dst]));
}

// ---------------- aggregation (denominator fused) ----------------
__global__ __launch_bounds__(256) void agg1_kernel(const float* __restrict__ bias) {
    int i = blockIdx.x;
    int tid = threadIdx.x;          // 0..255
    int hh = tid >> 6;              // head
    int beg = g_off[i];
    int end = g_off[i + 1];
    float acc = 0.f, sw = 0.f;
    if (beg < end) {
        int src = g_csr_src[beg];
        float w = g_wex1[(size_t)beg * H1 + hh];
        for (int k = beg; k + 1 < end; k++) {
            int src2 = g_csr_src[k + 1];
            float w2 = g_wex1[(size_t)(k + 1) * H1 + hh];
            acc += w * g_h1[(size_t)src * HC1 + tid];
            sw += w;
            src = src2; w = w2;
        }
        acc += w * g_h1[(size_t)src * HC1 + tid];
        sw += w;
    }
    float es = expf(leaky(g_as1[i * H1 + hh] + g_ad1[i * H1 + hh]));
    acc += es * g_h1[(size_t)i * HC1 + tid];
    sw += es;
    float o = acc / (sw + 1e-16f) + bias[tid];
    g_agg1[(size_t)i * HC1 + tid] = fmaxf(o, 0.f);
}

__global__ __launch_bounds__(256) void agg2_kernel(const float* __restrict__ bias,
                                                   float* __restrict__ out) {
    int i = blockIdx.x * 4 + (threadIdx.x >> 6);
    int c = threadIdx.x & 63;
    if (i >= NN) return;
    int beg = g_off[i];
    int end = g_off[i + 1];
    float acc = 0.f, sw = 0.f;
    if (beg < end) {
        int src = g_csr_src[beg];
        float w = g_wex2[beg];
        for (int k = beg; k + 1 < end; k++) {
            int src2 = g_csr_src[k + 1];
            float w2 = g_wex2[k + 1];
            acc += w * g_h2[(size_t)src * CC + c];
            sw += w;
            src = src2; w = w2;
        }
        acc += w * g_h2[(size_t)src * CC + c];
        sw += w;
    }
    float es = expf(leaky(g_as2[i] + g_ad2[i]));
    acc += es * g_h2[(size_t)i * CC + c];
    sw += es;
    out[(size_t)i * CC + c] = acc / (sw + 1e-16f) + bias[c];
}

// ---------------- launch ----------------
extern "C" void kernel_launch(void* const* d_in, const int* in_sizes, int n_in,
                              void* d_out, int out_size) {
    const float* x     = (const float*)d_in[0];
    const void*  ei    = d_in[1];
    const float* W1    = (const float*)d_in[2];
    const float* asrc1 = (const float*)d_in[3];
    const float* adst1 = (const float*)d_in[4];
    const float* b1    = (const float*)d_in[5];
    const float* W2    = (const float*)d_in[6];
    const float* asrc2 = (const float*)d_in[7];
    const float* adst2 = (const float*)d_in[8];
    const float* b2    = (const float*)d_in[9];
    float* out = (float*)d_out;

    // ---- CSR histogram + scan (independent of gemm1) ----
    detect_kernel<<<1, 1>>>(ei);
    zero_deg_kernel<<<(NN + 255) / 256, 256>>>();
    count_kernel<<<(EE + 255) / 256, 256>>>(ei);
    scan_partial_kernel<<<NB_SCAN, 256>>>();
    scan_tops_kernel<<<1, 256>>>();
    scan_apply_kernel<<<NB_SCAN, 256>>>();

    // ---- layer 1 ----
    {
        dim3 g((NN + 127) / 128, H1);
        gemm1_kernel<<<g, 128>>>(x, W1, asrc1, adst1);
    }
    scatter_kernel<<<(EE + 255) / 256, 256>>>(ei);  // also computes wex1
    agg1_kernel<<<NN, 256>>>(b1);

    // ---- layer 2 ----
    {
        dim3 g((NN + 127) / 128, 1);
        gemm2_kernel<<<g, 128>>>(W2, asrc2, adst2);
    }
    edge_kernel_l2<<<(EE + 255) / 256, 256>>>();
    agg2_kernel<<<(NN + 3) / 4, 256>>>(b2, out);
}